// round 5
// baseline (speedup 1.0000x reference)
#include <cuda_runtime.h>

// GatedDeltaRuleModule: 5-tap causal local attention, fully memory-bound.
// B=2, S=8192, H=16, D=128, W=4 (conv_kernel_size).
// out[b,s,h,:] = sum_{d=0..4} (q_s . k_{s-d}) * scale * sigmoid(a_s * b_{s-d}) * v_{s-d}
// out[b,0,h,:] = v[b,0,h,:]

#define BATCH 2
#define SEQ   8192
#define HEADS 16
#define DIM   128
#define WIN   4
#define TILE  32
#define THREADS 256
#define HALO_ROWS (TILE + WIN)

__device__ __forceinline__ float sigmoidf_fast(float x) {
    return 1.0f / (1.0f + __expf(-x));
}

__global__ __launch_bounds__(THREADS)
void gdr_local_attn_kernel(const float* __restrict__ q,
                           const float* __restrict__ k,
                           const float* __restrict__ v,
                           const float* __restrict__ a,
                           const float* __restrict__ b,
                           float* __restrict__ out)
{
    // k/v tiles with WIN-row halo on the left. Row r <-> global s = s0 - WIN + r.
    __shared__ float ks[HALO_ROWS * DIM];
    __shared__ float vs[HALO_ROWS * DIM];
    __shared__ float bsh[HALO_ROWS];
    __shared__ float ash[TILE];

    const int s0  = blockIdx.x * TILE;
    const int h   = blockIdx.y;
    const int bb  = blockIdx.z;
    const int tid = threadIdx.x;

    const float SCALE = 0.08838834764831845f;  // 1/sqrt(128)

    // ---- Cooperative tile load (float4, fully coalesced: 32 lanes cover one 512B row) ----
    for (int idx = tid; idx < HALO_ROWS * (DIM / 4); idx += THREADS) {
        const int r  = idx >> 5;         // DIM/4 = 32 float4 per row
        const int c4 = idx & 31;
        const int s  = s0 - WIN + r;
        float4 kk = make_float4(0.f, 0.f, 0.f, 0.f);
        float4 vv = kk;
        if (s >= 0) {
            const size_t base = ((((size_t)bb * SEQ + s) * HEADS) + h) * DIM + c4 * 4;
            kk = *reinterpret_cast<const float4*>(k + base);
            vv = *reinterpret_cast<const float4*>(v + base);
        }
        *reinterpret_cast<float4*>(ks + r * DIM + c4 * 4) = kk;
        *reinterpret_cast<float4*>(vs + r * DIM + c4 * 4) = vv;
    }
    for (int idx = tid; idx < HALO_ROWS; idx += THREADS) {
        const int s = s0 - WIN + idx;
        bsh[idx] = (s >= 0) ? b[((size_t)bb * SEQ + s) * HEADS + h] : 0.f;
        if (idx < TILE)
            ash[idx] = a[((size_t)bb * SEQ + s0 + idx) * HEADS + h];
    }
    __syncthreads();

    const int warp = tid >> 5;
    const int lane = tid & 31;

    // Each warp handles TILE/8 = 4 output rows; lane owns columns [4*lane, 4*lane+4).
    for (int i = warp; i < TILE; i += THREADS / 32) {
        const int s   = s0 + i;
        const int r_s = i + WIN;                      // smem row of position s
        const size_t rowbase = ((((size_t)bb * SEQ + s) * HEADS) + h) * DIM + lane * 4;
        const float4 q4 = *reinterpret_cast<const float4*>(q + rowbase);

        // 5 per-lane dot partials (LDS.128, conflict-free)
        float part[WIN + 1];
#pragma unroll
        for (int d = 0; d <= WIN; d++) {
            const float4 k4 = *reinterpret_cast<const float4*>(ks + (r_s - d) * DIM + lane * 4);
            part[d] = q4.x * k4.x + q4.y * k4.y + q4.z * k4.z + q4.w * k4.w;
        }
        // Batched butterfly reduction over the warp (ILP across the 5 taps)
#pragma unroll
        for (int off = 16; off > 0; off >>= 1) {
#pragma unroll
            for (int d = 0; d <= WIN; d++)
                part[d] += __shfl_xor_sync(0xffffffffu, part[d], off);
        }

        const float av = ash[i];
        float4 acc = make_float4(0.f, 0.f, 0.f, 0.f);
#pragma unroll
        for (int d = 0; d <= WIN; d++) {
            // For s-d < 0 the halo was zero-filled: part[d]==0 -> contribution 0,
            // exactly matching the reference's zero-padding. No branch needed.
            const float g     = sigmoidf_fast(av * bsh[r_s - d]);
            const float coeff = part[d] * SCALE * g;
            const float4 v4 = *reinterpret_cast<const float4*>(vs + (r_s - d) * DIM + lane * 4);
            acc.x += coeff * v4.x;
            acc.y += coeff * v4.y;
            acc.z += coeff * v4.z;
            acc.w += coeff * v4.w;
        }

        if (s == 0) {  // reference special-cases position 0: out = v_0
            acc = *reinterpret_cast<const float4*>(vs + WIN * DIM + lane * 4);
        }

        *reinterpret_cast<float4*>(out + rowbase) = acc;
    }
}

extern "C" void kernel_launch(void* const* d_in, const int* in_sizes, int n_in,
                              void* d_out, int out_size)
{
    const float* q = (const float*)d_in[0];
    const float* k = (const float*)d_in[1];
    const float* v = (const float*)d_in[2];
    const float* a = (const float*)d_in[3];
    const float* b = (const float*)d_in[4];
    float* out = (float*)d_out;

    dim3 grid(SEQ / TILE, HEADS, BATCH);  // (256, 16, 2) = 8192 blocks
    gdr_local_attn_kernel<<<grid, THREADS>>>(q, k, v, a, b, out);
}